// round 15
// baseline (speedup 1.0000x reference)
#include <cuda_runtime.h>
#include <cuda_fp16.h>
#include <stdint.h>

// Hash-grid trilinear interpolation — THREE-pass table slicing, fp16 partial
// scratch (accumulated across passes), serpentine pass order.
//
// Pass k gathers only corners whose bucket lies in table slice k (~43MB).
// Narrower slice => per-pass L2 fill (slice + streaming) fits ~126MB L2, so
// the ~1.3 expected repeat touches per bucket per pass become L2 hits and
// gather DRAM approaches the per-pass compulsory floor (~45MB), vs ~126MB
// measured with 64MB slices (R13/R14).
//
// Pass 0 writes fp16 partials to scratch; pass 1 accumulates in scratch;
// pass 2 adds and writes out once (fp32). Passes alternate direction
// (fwd/rev/fwd) so each pass starts on the previous pass's still-L2-resident
// scratch tail.
//
// Thread = (point, 16B feature half): lane pairs share each 32B gather sector.

#define BUCKETS     (1u << 22)
#define BUCKETS_MASK (BUCKETS - 1u)
#define P1 1u
#define P2 2654435761u
#define P3 805459861u
#define MAX_PTS 2100000

// 3 slice boundaries (~1398101 buckets each)
#define S1 1398102u
#define S2 2796204u

__device__ uint2 g_part[(size_t)MAX_PTS * 2];   // fp16x4 partial per (pt,half) task

__device__ __forceinline__ float4 ldg_line128(const void* p) {
    float4 v;
    asm("ld.global.nc.L2::128B.v4.f32 {%0,%1,%2,%3}, [%4];"
        : "=f"(v.x), "=f"(v.y), "=f"(v.z), "=f"(v.w)
        : "l"(p), "l"((const void*)0) : );
    return v;
}

__device__ __forceinline__ float4 ldg_nc(const void* p) {
    float4 v;
    asm("ld.global.nc.L2::128B.v4.f32 {%0,%1,%2,%3}, [%4];"
        : "=f"(v.x), "=f"(v.y), "=f"(v.z), "=f"(v.w)
        : "l"(p));
    return v;
}

__device__ __forceinline__ void point_setup(
    const float* __restrict__ pts, int pt, uint32_t& h, float* w)
{
    float x = pts[3 * pt + 0];
    float y = pts[3 * pt + 1];
    float z = pts[3 * pt + 2];
    float qx = x * 1024.0f, qy = y * 1024.0f, qz = z * 1024.0f;
    float bxf = floorf(qx), byf = floorf(qy), bzf = floorf(qz);
    float fx = qx - bxf, fy = qy - byf, fz = qz - bzf;
    h = (uint32_t)(int)bxf * P1 + (uint32_t)(int)byf * P2 + (uint32_t)(int)bzf * P3;
    float gx = 1.0f - fx, gy = 1.0f - fy, gz = 1.0f - fz;
    w[0] = gx * gy * gz;  w[1] = fx * gy * gz;
    w[2] = gx * fy * gz;  w[3] = fx * fy * gz;
    w[4] = gx * gy * fz;  w[5] = fx * gy * fz;
    w[6] = gx * fy * fz;  w[7] = fx * fy * fz;
}

__device__ __forceinline__ float4 gather_range(
    const char* __restrict__ vf, uint32_t h, uint32_t half,
    const float* w, uint32_t lo, uint32_t hi)
{
    const uint32_t hoff[8] = {0u, P1, P2, P1 + P2, P3, P1 + P3, P2 + P3, P1 + P2 + P3};
    const char* bptr = vf + (half << 4);
    float4 f[8];
#pragma unroll
    for (int c = 0; c < 8; c++) {
        uint32_t vid = (h + hoff[c]) & BUCKETS_MASK;
        f[c] = make_float4(0.f, 0.f, 0.f, 0.f);
        if (vid >= lo && vid < hi)
            f[c] = ldg_nc(bptr + ((size_t)vid << 5));
    }
    float4 acc = make_float4(0.f, 0.f, 0.f, 0.f);
#pragma unroll
    for (int c = 0; c < 8; c++) {
        acc.x = fmaf(w[c], f[c].x, acc.x);
        acc.y = fmaf(w[c], f[c].y, acc.y);
        acc.z = fmaf(w[c], f[c].z, acc.z);
        acc.w = fmaf(w[c], f[c].w, acc.w);
    }
    return acc;
}

__device__ __forceinline__ uint2 pack_h4(float4 a) {
    __half2 lo = __float22half2_rn(make_float2(a.x, a.y));
    __half2 hi = __float22half2_rn(make_float2(a.z, a.w));
    uint2 p;
    p.x = *reinterpret_cast<uint32_t*>(&lo);
    p.y = *reinterpret_cast<uint32_t*>(&hi);
    return p;
}

__device__ __forceinline__ float4 unpack_h4(uint2 p) {
    __half2 lo = *reinterpret_cast<__half2*>(&p.x);
    __half2 hi = *reinterpret_cast<__half2*>(&p.y);
    float2 a = __half22float2(lo);
    float2 b = __half22float2(hi);
    return make_float4(a.x, a.y, b.x, b.y);
}

// PASS 0 (forward): gather slice [0,S1), write fp16 partial.
__global__ void __launch_bounds__(256) pass0_kernel(
    const float* __restrict__ pts, const char* __restrict__ vf, int n)
{
    int s = blockIdx.x * blockDim.x + threadIdx.x;
    int pt = s >> 1, half = s & 1;
    if (pt >= n) return;
    uint32_t h; float w[8];
    point_setup(pts, pt, h, w);
    float4 acc = gather_range(vf, h, half, w, 0u, S1);
    g_part[s] = pack_h4(acc);
}

// PASS 1 (reversed): gather slice [S1,S2), accumulate into scratch.
__global__ void __launch_bounds__(256) pass1_kernel(
    const float* __restrict__ pts, const char* __restrict__ vf, int n)
{
    int s = blockIdx.x * blockDim.x + threadIdx.x;
    int total = 2 * n;
    if (s >= total) return;
    s = total - 1 - s;
    int pt = s >> 1, half = s & 1;
    uint32_t h; float w[8];
    point_setup(pts, pt, h, w);
    float4 acc = gather_range(vf, h, half, w, S1, S2);
    float4 p = unpack_h4(__ldcg(&g_part[s]));
    acc.x += p.x; acc.y += p.y; acc.z += p.z; acc.w += p.w;
    g_part[s] = pack_h4(acc);
}

// PASS 2 (forward): gather slice [S2,BUCKETS), add scratch, write out fp32.
__global__ void __launch_bounds__(256) pass2_kernel(
    const float* __restrict__ pts, const char* __restrict__ vf,
    float4* __restrict__ out, int n)
{
    int s = blockIdx.x * blockDim.x + threadIdx.x;
    int pt = s >> 1, half = s & 1;
    if (pt >= n) return;
    uint32_t h; float w[8];
    point_setup(pts, pt, h, w);
    float4 acc = gather_range(vf, h, half, w, S2, BUCKETS);
    float4 p = unpack_h4(__ldcg(&g_part[s]));
    acc.x += p.x; acc.y += p.y; acc.z += p.z; acc.w += p.w;
    __stcs(out + 2 * (size_t)pt + half, acc);
}

// Exact fp32 two-pass fallback through out if n exceeds scratch capacity.
template <int PASS>
__global__ void __launch_bounds__(256) fallback_kernel(
    const float* __restrict__ pts, const char* __restrict__ vf,
    float4* __restrict__ out, int n)
{
    int s = blockIdx.x * blockDim.x + threadIdx.x;
    int pt = s >> 1, half = s & 1;
    if (pt >= n) return;
    uint32_t h; float w[8];
    point_setup(pts, pt, h, w);
    uint32_t lo = (PASS == 0) ? 0u : (BUCKETS >> 1);
    uint32_t hi = (PASS == 0) ? (BUCKETS >> 1) : BUCKETS;
    float4 acc = gather_range(vf, h, half, w, lo, hi);
    float4* op = out + 2 * (size_t)pt + half;
    if (PASS == 0) {
        *op = acc;
    } else {
        float4 p = *op;
        acc.x += p.x; acc.y += p.y; acc.z += p.z; acc.w += p.w;
        __stcs(op, acc);
    }
}

extern "C" void kernel_launch(void* const* d_in, const int* in_sizes, int n_in,
                              void* d_out, int out_size)
{
    const float* pts = (const float*)d_in[0];
    const char*  vf  = (const char*)d_in[1];
    float4*      out = (float4*)d_out;

    int n = in_sizes[0] / 3;
    int total = 2 * n;
    int block = 256;
    int grid = (total + block - 1) / block;

    if (n > MAX_PTS) {
        fallback_kernel<0><<<grid, block>>>(pts, vf, out, n);
        fallback_kernel<1><<<grid, block>>>(pts, vf, out, n);
        return;
    }

    pass0_kernel<<<grid, block>>>(pts, vf, n);
    pass1_kernel<<<grid, block>>>(pts, vf, n);
    pass2_kernel<<<grid, block>>>(pts, vf, out, n);
}

// round 16
// speedup vs baseline: 1.4068x; 1.4068x over previous
#include <cuda_runtime.h>
#include <cuda_fp16.h>
#include <stdint.h>

// Hash-grid trilinear interpolation — fp16 table copy in scratch + ONE pass.
//
// Kernel A streams the 128MB fp32 table into a 64MB fp16 __device__ copy.
// Kernel B then interpolates in a single pass: the 64MB table plus ~88MB of
// streaming traffic gives a bucket inter-touch reuse distance of ~10MB, far
// under the ~126MB L2, so all ~3.8x bucket reuse is captured by plain LRU and
// gather DRAM collapses to the ~64MB compulsory fill. No slicing, no partial
// scratch (fp32 accumulation end-to-end), no duplicated point setup.
//
// R15 calibration: per-pass overhead floor ~30-35us makes >2 passes a loss;
// the binding limits are the 16M-corner-touch L1 wavefront floor (~57us) and
// random-sector DRAM (~4TB/s). This design drops DRAM far below L1 so only
// the wavefront floor remains.
//
// B layout: thread = (point, 8B fp16 feature half); lane pairs (halves of the
// same point) merge each corner access into one 16B transaction.

#define BUCKETS (1u << 22)
#define BUCKETS_MASK (BUCKETS - 1u)
#define P1 1u
#define P2 2654435761u
#define P3 805459861u

__device__ uint4 g_vf16[BUCKETS];   // 64 MB: bucket-major, 8 fp16 per bucket

__device__ __forceinline__ uint32_t h2_bits(__half2 h) {
    return *reinterpret_cast<uint32_t*>(&h);
}

// A: fp32 table -> fp16 scratch copy. Pure streaming (192MB).
__global__ void __launch_bounds__(256) convert_kernel(
    const float4* __restrict__ vf, int nbuckets)
{
    int i = blockIdx.x * blockDim.x + threadIdx.x;
    if (i >= nbuckets) return;
    float4 a = __ldcs(vf + 2 * (size_t)i);
    float4 b = __ldcs(vf + 2 * (size_t)i + 1);
    uint4 o;
    o.x = h2_bits(__float22half2_rn(make_float2(a.x, a.y)));
    o.y = h2_bits(__float22half2_rn(make_float2(a.z, a.w)));
    o.z = h2_bits(__float22half2_rn(make_float2(b.x, b.y)));
    o.w = h2_bits(__float22half2_rn(make_float2(b.z, b.w)));
    g_vf16[i] = o;   // plain store: dirty in L2, warm start for B
}

// B: single-pass interpolation from the L2-resident fp16 table.
__global__ void __launch_bounds__(256) interp16_kernel(
    const float* __restrict__ pts,   // (N,3)
    float4* __restrict__ out,        // (N, 8 fp32) = 2 float4 per point
    int n)
{
    int s = blockIdx.x * blockDim.x + threadIdx.x;
    int pt = s >> 1, half = s & 1;
    if (pt >= n) return;

    float x = pts[3 * pt + 0];
    float y = pts[3 * pt + 1];
    float z = pts[3 * pt + 2];
    float qx = x * 1024.0f, qy = y * 1024.0f, qz = z * 1024.0f;
    float bxf = floorf(qx), byf = floorf(qy), bzf = floorf(qz);
    float fx = qx - bxf, fy = qy - byf, fz = qz - bzf;
    uint32_t h = (uint32_t)(int)bxf * P1
               + (uint32_t)(int)byf * P2
               + (uint32_t)(int)bzf * P3;

    float gx = 1.0f - fx, gy = 1.0f - fy, gz = 1.0f - fz;
    float w[8];
    w[0] = gx * gy * gz;  w[1] = fx * gy * gz;
    w[2] = gx * fy * gz;  w[3] = fx * fy * gz;
    w[4] = gx * gy * fz;  w[5] = fx * gy * fz;
    w[6] = gx * fy * fz;  w[7] = fx * fy * fz;

    const uint32_t hoff[8] = {0u, P1, P2, P1 + P2, P3, P1 + P3, P2 + P3, P1 + P2 + P3};
    // half h of bucket v = 8 bytes at byte offset v*16 + h*8
    const uint2* tab = reinterpret_cast<const uint2*>(g_vf16) + half;

    // Issue all 8 gathers (8B each; lane pairs merge to 16B) before consuming.
    uint2 raw[8];
#pragma unroll
    for (int c = 0; c < 8; c++) {
        uint32_t vid = (h + hoff[c]) & BUCKETS_MASK;
        raw[c] = __ldg(tab + 2 * (size_t)vid);
    }

    float4 acc = make_float4(0.f, 0.f, 0.f, 0.f);
#pragma unroll
    for (int c = 0; c < 8; c++) {
        __half2 h0 = *reinterpret_cast<__half2*>(&raw[c].x);
        __half2 h1 = *reinterpret_cast<__half2*>(&raw[c].y);
        float2 f01 = __half22float2(h0);
        float2 f23 = __half22float2(h1);
        float wc = w[c];
        acc.x = fmaf(wc, f01.x, acc.x);
        acc.y = fmaf(wc, f01.y, acc.y);
        acc.z = fmaf(wc, f23.x, acc.z);
        acc.w = fmaf(wc, f23.y, acc.w);
    }

    __stcs(out + 2 * (size_t)pt + half, acc);
}

extern "C" void kernel_launch(void* const* d_in, const int* in_sizes, int n_in,
                              void* d_out, int out_size)
{
    const float*  pts = (const float*)d_in[0];
    const float4* vf  = (const float4*)d_in[1];
    float4*       out = (float4*)d_out;

    int n = in_sizes[0] / 3;

    int blockA = 256;
    int gridA = (BUCKETS + blockA - 1) / blockA;
    convert_kernel<<<gridA, blockA>>>(vf, BUCKETS);

    int total = 2 * n;
    int blockB = 256;
    int gridB = (total + blockB - 1) / blockB;
    interp16_kernel<<<gridB, blockB>>>(pts, out, n);
}

// round 17
// speedup vs baseline: 1.4073x; 1.0004x over previous
#include <cuda_runtime.h>
#include <cuda_fp16.h>
#include <stdint.h>

// Hash-grid trilinear interpolation — fp16 table in scratch + quad-lane
// pair-merged gathers.
//
// Kernel A: stream fp32 table (128MB) -> fp16 scratch copy (64MB). The fp16
// table + ~88MB streaming fits L2, so gather DRAM = compulsory only (R16).
//
// Kernel B: thread = (point, quarter q). Corner pair (2p,2p+1) = buckets
// vid, vid+1 = 32 CONTIGUOUS bytes of the fp16 table; the 4 lanes of a
// point-quad each load 8B of that block in the SAME LDG instruction, so L1
// merges the pair into ~1 wavefront (line-split prob 1/8). 4 pair-loads per
// point instead of 8 corner-loads -> L1 wavefront floor halves (57->~30us),
// which R16 showed is the binding limit.
//
// Thread q accumulates corner c = 2p+(q>>1), feature half (q&1); a single
// shfl_xor(2) float4 reduction combines even/odd corners; lanes q<2 store.

#define BUCKETS (1u << 22)
#define BUCKETS_MASK (BUCKETS - 1u)
#define P1 1u
#define P2 2654435761u
#define P3 805459861u

__device__ uint4 g_vf16[BUCKETS];   // 64 MB: bucket-major, 8 fp16 per bucket

__device__ __forceinline__ uint32_t h2_bits(__half2 h) {
    return *reinterpret_cast<uint32_t*>(&h);
}

// A: fp32 table -> fp16 scratch copy. Pure streaming (192MB).
__global__ void __launch_bounds__(256) convert_kernel(
    const float4* __restrict__ vf, int nbuckets)
{
    int i = blockIdx.x * blockDim.x + threadIdx.x;
    if (i >= nbuckets) return;
    float4 a = __ldcs(vf + 2 * (size_t)i);
    float4 b = __ldcs(vf + 2 * (size_t)i + 1);
    uint4 o;
    o.x = h2_bits(__float22half2_rn(make_float2(a.x, a.y)));
    o.y = h2_bits(__float22half2_rn(make_float2(a.z, a.w)));
    o.z = h2_bits(__float22half2_rn(make_float2(b.x, b.y)));
    o.w = h2_bits(__float22half2_rn(make_float2(b.z, b.w)));
    g_vf16[i] = o;   // plain store: dirty in L2, warm start for B
}

// B: quad-lane interpolation from the L2-resident fp16 table.
__global__ void __launch_bounds__(256) interp_quad_kernel(
    const float* __restrict__ pts,   // (N,3)
    float4* __restrict__ out,        // (N, 8 fp32) = 2 float4 per point
    int n)
{
    int s = blockIdx.x * blockDim.x + threadIdx.x;
    int pt = s >> 2;
    int q  = s & 3;                  // quarter within the point
    if (pt >= n) return;

    // broadcast point load (4 lanes same address -> merged)
    float x = pts[3 * pt + 0];
    float y = pts[3 * pt + 1];
    float z = pts[3 * pt + 2];

    float qx = x * 1024.0f, qy = y * 1024.0f, qz = z * 1024.0f;
    float bxf = floorf(qx), byf = floorf(qy), bzf = floorf(qz);
    float fx = qx - bxf, fy = qy - byf, fz = qz - bzf;
    uint32_t h = (uint32_t)(int)bxf * P1
               + (uint32_t)(int)byf * P2
               + (uint32_t)(int)bzf * P3;

    float gx = 1.0f - fx, gy = 1.0f - fy, gz = 1.0f - fz;
    // weight of corner 2p + (q>>1) for pair p; corner parity = x-offset
    float wxq = (q >> 1) ? fx : gx;
    float wp[4];
    wp[0] = wxq * gy * gz;   // pair 0: (.,0,0)
    wp[1] = wxq * fy * gz;   // pair 1: (.,1,0)
    wp[2] = wxq * gy * fz;   // pair 2: (.,0,1)
    wp[3] = wxq * fy * fz;   // pair 3: (.,1,1)

    // even-corner hash offsets per pair
    const uint32_t poff[4] = {0u, P2, P3, P2 + P3};

    const char* tab = (const char*)g_vf16;
    uint32_t csel = (uint32_t)(q >> 1);        // which bucket of the pair
    uint32_t hsel = (uint32_t)(q & 1);         // which 8B half of the bucket

    // Issue all 4 pair-loads first (one LDG.64 instr covers a 32B pair block
    // across the 4 quad lanes -> ~1 L1 wavefront per point per instruction).
    uint2 raw[4];
#pragma unroll
    for (int p = 0; p < 4; p++) {
        uint32_t vid0 = (h + poff[p]) & BUCKETS_MASK;
        uint32_t vid  = (vid0 + csel) & BUCKETS_MASK;   // handles wrap at mask
        raw[p] = __ldg((const uint2*)(tab + ((size_t)vid << 4) + (hsel << 3)));
    }

    float4 acc = make_float4(0.f, 0.f, 0.f, 0.f);
#pragma unroll
    for (int p = 0; p < 4; p++) {
        __half2 h0 = *reinterpret_cast<__half2*>(&raw[p].x);
        __half2 h1 = *reinterpret_cast<__half2*>(&raw[p].y);
        float2 f01 = __half22float2(h0);
        float2 f23 = __half22float2(h1);
        float wc = wp[p];
        acc.x = fmaf(wc, f01.x, acc.x);
        acc.y = fmaf(wc, f01.y, acc.y);
        acc.z = fmaf(wc, f23.x, acc.z);
        acc.w = fmaf(wc, f23.y, acc.w);
    }

    // combine even-corner (q<2) and odd-corner (q>=2) partials per half
    acc.x += __shfl_xor_sync(0xFFFFFFFFu, acc.x, 2);
    acc.y += __shfl_xor_sync(0xFFFFFFFFu, acc.y, 2);
    acc.z += __shfl_xor_sync(0xFFFFFFFFu, acc.z, 2);
    acc.w += __shfl_xor_sync(0xFFFFFFFFu, acc.w, 2);

    // lanes q=0 (features 0-3) and q=1 (features 4-7) store; coalesced 256B/warp
    if (q < 2) {
        __stcs(out + 2 * (size_t)pt + q, acc);
    }
}

extern "C" void kernel_launch(void* const* d_in, const int* in_sizes, int n_in,
                              void* d_out, int out_size)
{
    const float*  pts = (const float*)d_in[0];
    const float4* vf  = (const float4*)d_in[1];
    float4*       out = (float4*)d_out;

    int n = in_sizes[0] / 3;

    int blockA = 256;
    int gridA = (BUCKETS + blockA - 1) / blockA;
    convert_kernel<<<gridA, blockA>>>(vf, BUCKETS);

    long long total = 4LL * n;
    int blockB = 256;
    long long gridB = (total + blockB - 1) / blockB;
    interp_quad_kernel<<<(int)gridB, blockB>>>(pts, out, n);
}